// round 1
// baseline (speedup 1.0000x reference)
#include <cuda_runtime.h>
#include <cuda_bf16.h>

// ---------------------------------------------------------------------------
// Submanifold sparse conv, 2 layers, C=64, K=3^3=27 offsets, N=200000 voxels.
// Fixed problem constants (per reference):
//   N=200000, C=64, SHAPE=(128,128,128), B=2, KV=27
// ---------------------------------------------------------------------------

#define N_VOX   200000
#define C_CH    64
#define KV_     27
#define DD      128
#define BATCH   2
#define GRID_CELLS (BATCH * DD * DD * DD)   // 4,194,304

// Scratch (device globals -- no allocation allowed in kernel_launch)
__device__ int   g_grid[GRID_CELLS];        // dense coord -> voxel row (or -1)
__device__ int   g_nb[KV_ * N_VOX];         // rulebook: nb[k*N + n]
__device__ float g_mid[N_VOX * C_CH];       // layer-0 output

// ---------------------------------------------------------------------------
// 1) init grid to -1
// ---------------------------------------------------------------------------
__global__ void init_grid_kernel() {
    int i = blockIdx.x * blockDim.x + threadIdx.x;
    int stride = gridDim.x * blockDim.x;
    for (; i < GRID_CELLS; i += stride) g_grid[i] = -1;
}

// ---------------------------------------------------------------------------
// 2) scatter voxel indices. Reference (.at[flat].set(arange), sequential
//    scatter) resolves duplicate coordinates as LAST-index-wins == max index.
//    atomicMax reproduces that deterministically.
// ---------------------------------------------------------------------------
__global__ void scatter_kernel(const int* __restrict__ coors) {
    int i = blockIdx.x * blockDim.x + threadIdx.x;
    if (i >= N_VOX) return;
    int b = coors[i * 4 + 0];
    int z = coors[i * 4 + 1];
    int y = coors[i * 4 + 2];
    int x = coors[i * 4 + 3];
    int flat = ((b * DD + z) * DD + y) * DD + x;
    atomicMax(&g_grid[flat], i);
}

// ---------------------------------------------------------------------------
// 3) rulebook: for each voxel, the 27 neighbor row indices (or -1)
//    offset order matches meshgrid(ax,ax,ax,indexing='ij'):
//    k = ((dz+1)*3 + (dy+1))*3 + (dx+1)
// ---------------------------------------------------------------------------
__global__ void build_nb_kernel(const int* __restrict__ coors) {
    int i = blockIdx.x * blockDim.x + threadIdx.x;
    if (i >= N_VOX) return;
    int b = coors[i * 4 + 0];
    int z = coors[i * 4 + 1];
    int y = coors[i * 4 + 2];
    int x = coors[i * 4 + 3];
    int base = b * DD * DD * DD;
    int k = 0;
    #pragma unroll
    for (int dz = -1; dz <= 1; dz++)
        #pragma unroll
        for (int dy = -1; dy <= 1; dy++)
            #pragma unroll
            for (int dx = -1; dx <= 1; dx++) {
                int nz = z + dz, ny = y + dy, nx = x + dx;
                int nbv = -1;
                if ((unsigned)nz < DD && (unsigned)ny < DD && (unsigned)nx < DD)
                    nbv = g_grid[base + (nz * DD + ny) * DD + nx];
                g_nb[k * N_VOX + i] = nbv;
                k++;
            }
}

// ---------------------------------------------------------------------------
// 4) conv layer: out[n][o] = sum_k sum_c f[nb[k][n]][c] * W[k][c][o]
//
// Block = 256 threads (8 warps) handles TILE_V=128 voxels.
// Per offset k: block stages W[k] (64x64 fp32 = 16KB) in smem, then each warp
// walks its 16 voxels. Skip (idx<0) is warp-uniform. Feature row gathered as
// two coalesced 128B loads, broadcast with shfl; W read conflict-free from
// smem. Thread owns out channels {lane, lane+32} for each of its 16 voxels.
// ---------------------------------------------------------------------------
#define TILE_V 128
#define VPW    16   // voxels per warp

__global__ __launch_bounds__(256, 2)
void subm_conv_kernel(const float* __restrict__ fin,
                      const float* __restrict__ Wall,
                      float* __restrict__ fout)
{
    __shared__ float ws[C_CH * C_CH];   // 16 KB

    int tid  = threadIdx.x;
    int lane = tid & 31;
    int warp = tid >> 5;
    int v0   = blockIdx.x * TILE_V + warp * VPW;

    float acc0[VPW], acc1[VPW];
    #pragma unroll
    for (int j = 0; j < VPW; j++) { acc0[j] = 0.f; acc1[j] = 0.f; }

    for (int k = 0; k < KV_; k++) {
        __syncthreads();
        // stage W[k]: 4096 floats via float4 (256 thr x 4 float4)
        const float4* wsrc = (const float4*)(Wall + k * C_CH * C_CH);
        float4* wdst = (float4*)ws;
        #pragma unroll
        for (int j = 0; j < 4; j++) wdst[tid + j * 256] = wsrc[tid + j * 256];
        __syncthreads();

        const int* nbk = g_nb + k * N_VOX;
        #pragma unroll 1
        for (int j = 0; j < VPW; j++) {
            int n = v0 + j;
            if (n >= N_VOX) break;
            int idx = __ldg(&nbk[n]);
            if (idx < 0) continue;
            float f0 = fin[idx * C_CH + lane];
            float f1 = fin[idx * C_CH + 32 + lane];
            #pragma unroll
            for (int c = 0; c < 32; c++) {
                float fa = __shfl_sync(0xffffffffu, f0, c);
                acc0[j] = fmaf(fa, ws[c * 64 + lane],      acc0[j]);
                acc1[j] = fmaf(fa, ws[c * 64 + 32 + lane], acc1[j]);
            }
            #pragma unroll
            for (int c = 0; c < 32; c++) {
                float fa = __shfl_sync(0xffffffffu, f1, c);
                acc0[j] = fmaf(fa, ws[(c + 32) * 64 + lane],      acc0[j]);
                acc1[j] = fmaf(fa, ws[(c + 32) * 64 + 32 + lane], acc1[j]);
            }
        }
    }

    #pragma unroll
    for (int j = 0; j < VPW; j++) {
        int n = v0 + j;
        if (n < N_VOX) {
            fout[n * C_CH + lane]      = acc0[j];
            fout[n * C_CH + 32 + lane] = acc1[j];
        }
    }
}

// ---------------------------------------------------------------------------
// launch
// ---------------------------------------------------------------------------
extern "C" void kernel_launch(void* const* d_in, const int* in_sizes, int n_in,
                              void* d_out, int out_size)
{
    const float* feats = (const float*)d_in[0];   // [N, 64]
    const int*   coors = (const int*)d_in[1];     // [N, 4]
    const float* W0    = (const float*)d_in[2];   // [27, 64, 64]
    const float* W1    = (const float*)d_in[3];   // [27, 64, 64]
    float*       out   = (float*)d_out;           // [N, 64]

    init_grid_kernel<<<1024, 256>>>();
    scatter_kernel<<<(N_VOX + 255) / 256, 256>>>(coors);
    build_nb_kernel<<<(N_VOX + 255) / 256, 256>>>(coors);

    int conv_blocks = (N_VOX + TILE_V - 1) / TILE_V;
    subm_conv_kernel<<<conv_blocks, 256>>>(feats, W0, g_mid);
    subm_conv_kernel<<<conv_blocks, 256>>>(g_mid, W1, out);
}

// round 2
// speedup vs baseline: 1.1103x; 1.1103x over previous
#include <cuda_runtime.h>
#include <cuda_bf16.h>

// Submanifold sparse conv, 2 layers, C=64, KV=27, N=200000, grid 128^3, B=2.

#define N_VOX   200000
#define C_CH    64
#define KV_     27
#define DD      128
#define BATCH   2
#define GRID_CELLS (BATCH * DD * DD * DD)
#define TILE_V  128
#define NBLK    ((N_VOX + TILE_V - 1) / TILE_V)

__device__ int   g_grid[GRID_CELLS];
__device__ int   g_nb[KV_ * N_VOX];
__device__ float g_mid[N_VOX * C_CH];

// ---------------------------------------------------------------- init grid
__global__ void init_grid_kernel() {
    int i = blockIdx.x * blockDim.x + threadIdx.x;
    int stride = gridDim.x * blockDim.x;
    int4* g4 = (int4*)g_grid;
    const int n4 = GRID_CELLS / 4;
    int4 v = make_int4(-1, -1, -1, -1);
    for (; i < n4; i += stride) g4[i] = v;
}

// ------------------------------------------------------------------ scatter
// Reference .at[flat].set(arange) = last-index-wins = max index on dups.
__global__ void scatter_kernel(const int* __restrict__ coors) {
    int i = blockIdx.x * blockDim.x + threadIdx.x;
    if (i >= N_VOX) return;
    int b = coors[i * 4 + 0];
    int z = coors[i * 4 + 1];
    int y = coors[i * 4 + 2];
    int x = coors[i * 4 + 3];
    int flat = ((b * DD + z) * DD + y) * DD + x;
    atomicMax(&g_grid[flat], i);
}

// ----------------------------------------------------------------- rulebook
__global__ void build_nb_kernel(const int* __restrict__ coors) {
    int i = blockIdx.x * blockDim.x + threadIdx.x;
    if (i >= N_VOX) return;
    int b = coors[i * 4 + 0];
    int z = coors[i * 4 + 1];
    int y = coors[i * 4 + 2];
    int x = coors[i * 4 + 3];
    int base = b * DD * DD * DD;
    int k = 0;
    #pragma unroll
    for (int dz = -1; dz <= 1; dz++)
        #pragma unroll
        for (int dy = -1; dy <= 1; dy++)
            #pragma unroll
            for (int dx = -1; dx <= 1; dx++) {
                int nz = z + dz, ny = y + dy, nx = x + dx;
                int nbv = -1;
                if ((unsigned)nz < DD && (unsigned)ny < DD && (unsigned)nx < DD)
                    nbv = __ldg(&g_grid[base + (nz * DD + ny) * DD + nx]);
                g_nb[k * N_VOX + i] = nbv;
                k++;
            }
}

// -------------------------------------------------------------- conv layer
// Per block: 128 output voxels, smem fp32 accumulator tile [128 x 64].
// Per offset k: compact valid pairs -> gather feature rows into smem ->
// warps run register-blocked GEMM on groups of 4 compacted voxels.
// Thread owns out channels {2*lane, 2*lane+1}. No shuffles, 1.25 instr/FMA.
#define SMEM_FLOATS (4096 + 8192 + 8192)
#define SMEM_BYTES  (SMEM_FLOATS * 4 + (128 + 128 + 1) * 4)

__global__ __launch_bounds__(256, 2)
void subm_conv_kernel(const float* __restrict__ fin,
                      const float* __restrict__ Wall,
                      float* __restrict__ fout)
{
    extern __shared__ float sm[];
    float* ws   = sm;            // W[k] staged, row-major [c][o]   (16 KB)
    float* fs   = sm + 4096;     // gathered features [<=128][64]   (32 KB)
    float* outs = sm + 12288;    // output accum [128][64]          (32 KB)
    int* in_idx   = (int*)(sm + SMEM_FLOATS);
    int* out_slot = in_idx + 128;
    int* mcnt     = out_slot + 128;

    const int tid  = threadIdx.x;
    const int lane = tid & 31;
    const int warp = tid >> 5;
    const int tile0 = blockIdx.x * TILE_V;

    // zero output accumulator
    float4* o4 = (float4*)outs;
    #pragma unroll
    for (int i = 0; i < 8; i++) o4[tid + i * 256] = make_float4(0.f, 0.f, 0.f, 0.f);

    const float4* fin4 = (const float4*)fin;
    float4*       fs4  = (float4*)fs;
    const float2* ws2  = (const float2*)ws;
    float2*       out2 = (float2*)outs;

    for (int k = 0; k < KV_; k++) {
        if (tid == 0) *mcnt = 0;
        __syncthreads();

        // stage W[k] (coalesced float4 copy) + compact valid pairs
        {
            const float4* wsrc = (const float4*)(Wall + k * 4096);
            float4* wdst = (float4*)ws;
            #pragma unroll
            for (int i = 0; i < 4; i++) wdst[tid + i * 256] = wsrc[tid + i * 256];
        }
        if (tid < TILE_V) {
            int n = tile0 + tid;
            int idx = (n < N_VOX) ? __ldg(&g_nb[k * N_VOX + n]) : -1;
            if (idx >= 0) {
                int p = atomicAdd(mcnt, 1);
                in_idx[p]   = idx;
                out_slot[p] = tid;
            }
        }
        __syncthreads();
        const int m = *mcnt;

        // gather feature rows of real pairs (16 threads per row)
        for (int p = tid >> 4; p < m; p += 16)
            fs4[p * 16 + (tid & 15)] = fin4[in_idx[p] * 16 + (tid & 15)];
        __syncthreads();

        // compute: groups of 4 compacted voxels per warp
        const int ngroups = (m + 3) >> 2;
        for (int g = warp; g < ngroups; g += 8) {
            const int p0 = g << 2;
            float2 a0 = make_float2(0.f, 0.f), a1 = a0, a2 = a0, a3 = a0;
            #pragma unroll
            for (int s = 0; s < 16; s++) {
                float4 fA = fs4[(p0 + 0) * 16 + s];
                float4 fB = fs4[(p0 + 1) * 16 + s];
                float4 fC = fs4[(p0 + 2) * 16 + s];
                float4 fD = fs4[(p0 + 3) * 16 + s];
                float2 w0 = ws2[(4 * s + 0) * 32 + lane];
                float2 w1 = ws2[(4 * s + 1) * 32 + lane];
                float2 w2 = ws2[(4 * s + 2) * 32 + lane];
                float2 w3 = ws2[(4 * s + 3) * 32 + lane];

                a0.x = fmaf(fA.x, w0.x, a0.x); a0.y = fmaf(fA.x, w0.y, a0.y);
                a0.x = fmaf(fA.y, w1.x, a0.x); a0.y = fmaf(fA.y, w1.y, a0.y);
                a0.x = fmaf(fA.z, w2.x, a0.x); a0.y = fmaf(fA.z, w2.y, a0.y);
                a0.x = fmaf(fA.w, w3.x, a0.x); a0.y = fmaf(fA.w, w3.y, a0.y);

                a1.x = fmaf(fB.x, w0.x, a1.x); a1.y = fmaf(fB.x, w0.y, a1.y);
                a1.x = fmaf(fB.y, w1.x, a1.x); a1.y = fmaf(fB.y, w1.y, a1.y);
                a1.x = fmaf(fB.z, w2.x, a1.x); a1.y = fmaf(fB.z, w2.y, a1.y);
                a1.x = fmaf(fB.w, w3.x, a1.x); a1.y = fmaf(fB.w, w3.y, a1.y);

                a2.x = fmaf(fC.x, w0.x, a2.x); a2.y = fmaf(fC.x, w0.y, a2.y);
                a2.x = fmaf(fC.y, w1.x, a2.x); a2.y = fmaf(fC.y, w1.y, a2.y);
                a2.x = fmaf(fC.z, w2.x, a2.x); a2.y = fmaf(fC.z, w2.y, a2.y);
                a2.x = fmaf(fC.w, w3.x, a2.x); a2.y = fmaf(fC.w, w3.y, a2.y);

                a3.x = fmaf(fD.x, w0.x, a3.x); a3.y = fmaf(fD.x, w0.y, a3.y);
                a3.x = fmaf(fD.y, w1.x, a3.x); a3.y = fmaf(fD.y, w1.y, a3.y);
                a3.x = fmaf(fD.z, w2.x, a3.x); a3.y = fmaf(fD.z, w2.y, a3.y);
                a3.x = fmaf(fD.w, w3.x, a3.x); a3.y = fmaf(fD.w, w3.y, a3.y);
            }
            // accumulate into smem out tile (discard padded lanes: p >= m)
            if (p0 + 0 < m) {
                int s0 = out_slot[p0 + 0];
                float2 o = out2[s0 * 32 + lane]; o.x += a0.x; o.y += a0.y;
                out2[s0 * 32 + lane] = o;
            }
            if (p0 + 1 < m) {
                int s1 = out_slot[p0 + 1];
                float2 o = out2[s1 * 32 + lane]; o.x += a1.x; o.y += a1.y;
                out2[s1 * 32 + lane] = o;
            }
            if (p0 + 2 < m) {
                int s2 = out_slot[p0 + 2];
                float2 o = out2[s2 * 32 + lane]; o.x += a2.x; o.y += a2.y;
                out2[s2 * 32 + lane] = o;
            }
            if (p0 + 3 < m) {
                int s3 = out_slot[p0 + 3];
                float2 o = out2[s3 * 32 + lane]; o.x += a3.x; o.y += a3.y;
                out2[s3 * 32 + lane] = o;
            }
        }
        __syncthreads();
    }

    // writeback
    const int rem = min(TILE_V, N_VOX - tile0);
    float4* fout4 = (float4*)fout;
    for (int f = tid; f < rem * 16; f += 256)
        fout4[tile0 * 16 + f] = o4[f];
}

// ------------------------------------------------------------------- launch
extern "C" void kernel_launch(void* const* d_in, const int* in_sizes, int n_in,
                              void* d_out, int out_size)
{
    const float* feats = (const float*)d_in[0];
    const int*   coors = (const int*)d_in[1];
    const float* W0    = (const float*)d_in[2];
    const float* W1    = (const float*)d_in[3];
    float*       out   = (float*)d_out;

    cudaFuncSetAttribute(subm_conv_kernel,
                         cudaFuncAttributeMaxDynamicSharedMemorySize, SMEM_BYTES);

    init_grid_kernel<<<1024, 256>>>();
    scatter_kernel<<<(N_VOX + 255) / 256, 256>>>(coors);
    build_nb_kernel<<<(N_VOX + 255) / 256, 256>>>(coors);

    subm_conv_kernel<<<NBLK, 256, SMEM_BYTES>>>(feats, W0, g_mid);
    subm_conv_kernel<<<NBLK, 256, SMEM_BYTES>>>(g_mid, W1, out);
}